// round 6
// baseline (speedup 1.0000x reference)
#include <cuda_runtime.h>
#include <cuda_fp16.h>
#include <cstdint>

// ---------------------------------------------------------------------------
// out[m, c] = sum_f sin(2*pi*f*t[m])*As[c,f] + cos(2*pi*f*t[m])*Ac[c,f]
// GEMM: M = 262144, N = 256, K = 256 (K = [sin | cos] halves).
// mma.sync.m16n8k16 fp16->fp32. Persistent CTAs (1/SM), W fp16 in SMEM.
// R6: 512 threads / 16 warps (4 per SMSP) so LDSM latency and HMMA chains
// overlap across warps; warp tile 32x64 keeps regs ~120 (no spills, R5 hit
// the 255-reg cap). Single X buffer split by K-half (sin/cos) pipelined:
//   phase A: MMA sin-half + fill cos-half (same tile)
//   phase B: MMA cos-half + fill sin-half (next tile)
// ---------------------------------------------------------------------------

#define NT        512
#define MT        128
// SMEM layout (bytes):
//   W : 256 rows(c) x 256 k fp16, 512 B/row, XOR-swizzled -> 131072
//   X : 128 rows(m) x 256 k fp16, 512 B/row               ->  65536
//   F : 128 floats (freqs)                                ->    512
#define SW_OFF     0
#define SX_OFF     131072
#define SF_OFF     196608
#define SMEM_TOTAL 197120

static __device__ __forceinline__ uint32_t smem_u32(const void* p) {
    uint32_t a;
    asm("{ .reg .u64 t; cvta.to.shared.u64 t, %1; cvt.u32.u64 %0, t; }"
        : "=r"(a) : "l"(p));
    return a;
}

// byte offset of (row, 16B-chunk) in a 512 B/row tile with XOR swizzle:
// chunk' = chunk ^ (row & 7). Conflict-free for ldmatrix and the fills.
static __device__ __forceinline__ uint32_t swz(uint32_t row, uint32_t chunk) {
    return row * 512u + ((chunk ^ (row & 7u)) << 4);
}

#define LDSM_X4(r, addr) \
    asm volatile("ldmatrix.sync.aligned.m8n8.x4.shared.b16 {%0,%1,%2,%3}, [%4];" \
        : "=r"((r)[0]), "=r"((r)[1]), "=r"((r)[2]), "=r"((r)[3]) : "r"(addr))

#define MMA_16816(d, a, b0, b1) \
    asm volatile("mma.sync.aligned.m16n8k16.row.col.f32.f16.f16.f32 " \
        "{%0,%1,%2,%3}, {%4,%5,%6,%7}, {%8,%9}, {%0,%1,%2,%3};" \
        : "+f"((d)[0]), "+f"((d)[1]), "+f"((d)[2]), "+f"((d)[3]) \
        : "r"((a)[0]), "r"((a)[1]), "r"((a)[2]), "r"((a)[3]), \
          "r"(b0), "r"(b1))

// fill 4 freqs of sin (k=f) or cos (k=f+128) for one X row
template <bool USE_COS>
static __device__ __forceinline__ void fill_chunk4(char* xb, const float* sF,
                                                   float tv, int xrow, int f)
{
    const float4 fr = *reinterpret_cast<const float4*>(sF + f);
    float v0, v1, v2, v3, h, r, th;
    h = tv * fr.x; r = (h + 12582912.0f) - 12582912.0f;
    th = (h - r) * 6.283185307179586f; v0 = USE_COS ? __cosf(th) : __sinf(th);
    h = tv * fr.y; r = (h + 12582912.0f) - 12582912.0f;
    th = (h - r) * 6.283185307179586f; v1 = USE_COS ? __cosf(th) : __sinf(th);
    h = tv * fr.z; r = (h + 12582912.0f) - 12582912.0f;
    th = (h - r) * 6.283185307179586f; v2 = USE_COS ? __cosf(th) : __sinf(th);
    h = tv * fr.w; r = (h + 12582912.0f) - 12582912.0f;
    th = (h - r) * 6.283185307179586f; v3 = USE_COS ? __cosf(th) : __sinf(th);

    __half2 h0 = __floats2half2_rn(v0, v1);
    __half2 h1 = __floats2half2_rn(v2, v3);
    const uint32_t ch  = (uint32_t)(f >> 3) + (USE_COS ? 16u : 0u);
    const uint32_t off = ((uint32_t)(f >> 2) & 1u) << 3;   // 8B within chunk
    uint2 v;
    v.x = *reinterpret_cast<uint32_t*>(&h0);
    v.y = *reinterpret_cast<uint32_t*>(&h1);
    *reinterpret_cast<uint2*>(xb + swz((uint32_t)xrow, ch) + off) = v;
}

__global__ void __launch_bounds__(NT, 1)
fourier_mma_kernel(const float* __restrict__ t,
                   const float* __restrict__ freqs,
                   const float* __restrict__ As,
                   const float* __restrict__ Ac,
                   float* __restrict__ out,
                   int rows)
{
    extern __shared__ char smem[];
    char* sW  = smem + SW_OFF;
    char* sX  = smem + SX_OFF;
    float* sF = (float*)(smem + SF_OFF);
    const uint32_t uW = smem_u32(sW);
    const uint32_t uX = smem_u32(sX);

    const int tid  = threadIdx.x;
    const int lane = tid & 31;
    const int wid  = tid >> 5;

    // ---- one-time: freqs + W fp32->fp16 into swizzled SMEM ----------------
    if (tid < 128) sF[tid] = freqs[tid];
    for (int i = tid; i < 256 * 64; i += NT) {
        const int n  = i >> 6;
        const int j4 = i & 63;
        const int k0 = j4 << 2;
        const float* src = (k0 < 128) ? (As + n * 128 + k0)
                                      : (Ac + n * 128 + (k0 - 128));
        const float4 w = *reinterpret_cast<const float4*>(src);
        __half2 h0 = __floats2half2_rn(w.x, w.y);
        __half2 h1 = __floats2half2_rn(w.z, w.w);
        uint32_t byte = swz((uint32_t)n, (uint32_t)(j4 >> 1)) + ((uint32_t)(j4 & 1) << 3);
        uint2 v;
        v.x = *reinterpret_cast<uint32_t*>(&h0);
        v.y = *reinterpret_cast<uint32_t*>(&h1);
        *reinterpret_cast<uint2*>(sW + byte) = v;
    }

    // ---- per-thread constants ---------------------------------------------
    const int xrow = tid >> 2;                 // X fill: 4 threads per row
    const int f0   = (tid & 3) << 5;           // each covers 32 freqs

    const int wm = wid >> 2;                   // warp grid: 4 (M) x 4 (N)
    const int wn = wid & 3;
    const int gid = lane >> 2, tig = lane & 3;

    const int aRow0   = wm * 32 + (lane & 15);
    const int aHi     = lane >> 4;
    const int bRowOff = (lane & 7) + ((lane >> 4) << 3);
    const int bHi     = (lane >> 3) & 1;

    const int numTiles = rows / MT;            // 2048
    const int stride   = gridDim.x;
    int tile = blockIdx.x;
    if (tile >= numTiles) return;

    __syncthreads();                           // W + freqs visible

    // ---- prologue: sin half of first tile ---------------------------------
    {
        const float tv = t[tile * MT + xrow];
        #pragma unroll
        for (int j = 0; j < 8; j++)
            fill_chunk4<false>(sX, sF, tv, xrow, f0 + j * 4);
    }
    __syncthreads();

    for (; tile < numTiles; tile += stride) {
        const int  nextTile = tile + stride;
        const bool hasNext  = nextTile < numTiles;
        const float tvc = t[tile * MT + xrow];                        // cos fill
        const float tvn = hasNext ? t[nextTile * MT + xrow] : 0.0f;   // sin fill
        const int m0 = tile * MT;

        float acc[2][8][4];
        #pragma unroll
        for (int mi = 0; mi < 2; mi++)
            #pragma unroll
            for (int ni = 0; ni < 8; ni++)
                #pragma unroll
                for (int q = 0; q < 4; q++) acc[mi][ni][q] = 0.0f;

        // ==== phase A: MMA ks 0..7 (sin half) + fill cos half of this tile ==
        #pragma unroll
        for (int ks = 0; ks < 8; ks++) {
            uint32_t a[2][4];
            #pragma unroll
            for (int mi = 0; mi < 2; mi++) {
                const uint32_t row = (uint32_t)(aRow0 + mi * 16);
                LDSM_X4(a[mi], uX + swz(row, (uint32_t)(ks * 2 + aHi)));
            }
            uint32_t b[4][4];
            #pragma unroll
            for (int nt = 0; nt < 4; nt++) {
                const uint32_t n = (uint32_t)(wn * 64 + nt * 16 + bRowOff);
                LDSM_X4(b[nt], uW + swz(n, (uint32_t)(ks * 2 + bHi)));
            }
            #pragma unroll
            for (int mi = 0; mi < 2; mi++)
                #pragma unroll
                for (int ni = 0; ni < 8; ni++) {
                    const uint32_t* bb = &b[ni >> 1][(ni & 1) * 2];
                    MMA_16816(acc[mi][ni], a[mi], bb[0], bb[1]);
                }
            fill_chunk4<true>(sX, sF, tvc, xrow, f0 + ks * 4);
        }
        __syncthreads();   // cos half ready; sin half free

        // ==== phase B: MMA ks 8..15 (cos half) + fill sin half of next tile =
        #pragma unroll
        for (int ks = 8; ks < 16; ks++) {
            uint32_t a[2][4];
            #pragma unroll
            for (int mi = 0; mi < 2; mi++) {
                const uint32_t row = (uint32_t)(aRow0 + mi * 16);
                LDSM_X4(a[mi], uX + swz(row, (uint32_t)(ks * 2 + aHi)));
            }
            uint32_t b[4][4];
            #pragma unroll
            for (int nt = 0; nt < 4; nt++) {
                const uint32_t n = (uint32_t)(wn * 64 + nt * 16 + bRowOff);
                LDSM_X4(b[nt], uW + swz(n, (uint32_t)(ks * 2 + bHi)));
            }
            #pragma unroll
            for (int mi = 0; mi < 2; mi++)
                #pragma unroll
                for (int ni = 0; ni < 8; ni++) {
                    const uint32_t* bb = &b[ni >> 1][(ni & 1) * 2];
                    MMA_16816(acc[mi][ni], a[mi], bb[0], bb[1]);
                }
            if (hasNext)
                fill_chunk4<false>(sX, sF, tvn, xrow, f0 + (ks - 8) * 4);
        }
        __syncthreads();   // sin half of next tile ready; cos half free

        // ==== epilogue: regs -> gmem (STG.64) ===============================
        #pragma unroll
        for (int mi = 0; mi < 2; mi++) {
            const size_t mrow = (size_t)(m0 + wm * 32 + mi * 16 + gid);
            float* o0 = out + mrow * 256 + wn * 64 + tig * 2;
            #pragma unroll
            for (int ni = 0; ni < 8; ni++) {
                float2 v0, v1;
                v0.x = acc[mi][ni][0]; v0.y = acc[mi][ni][1];
                v1.x = acc[mi][ni][2]; v1.y = acc[mi][ni][3];
                *reinterpret_cast<float2*>(o0 + ni * 8)        = v0;   // row m
                *reinterpret_cast<float2*>(o0 + ni * 8 + 2048) = v1;   // row m+8
            }
        }
    }
}

extern "C" void kernel_launch(void* const* d_in, const int* in_sizes, int n_in,
                              void* d_out, int out_size)
{
    const float* t     = (const float*)d_in[0];
    const float* freqs = (const float*)d_in[1];
    const float* As    = (const float*)d_in[2];
    const float* Ac    = (const float*)d_in[3];
    float* out         = (float*)d_out;

    int sm_count = 148;
    cudaDeviceGetAttribute(&sm_count, cudaDevAttrMultiProcessorCount, 0);
    cudaFuncSetAttribute(fourier_mma_kernel,
                         cudaFuncAttributeMaxDynamicSharedMemorySize, SMEM_TOTAL);

    const int rows = in_sizes[0];          // B*L = 262144
    fourier_mma_kernel<<<sm_count, NT, SMEM_TOTAL>>>(t, freqs, As, Ac, out, rows);
}

// round 7
// speedup vs baseline: 1.0564x; 1.0564x over previous
#include <cuda_runtime.h>
#include <cuda_fp16.h>
#include <cstdint>

// ---------------------------------------------------------------------------
// out[m, c] = sum_f sin(2*pi*f*t[m])*As[c,f] + cos(2*pi*f*t[m])*Ac[c,f]
// GEMM: M = 262144, N = 256, K = 256 (K = [sin | cos] halves).
// mma.sync.m16n8k16 fp16->fp32. Persistent CTAs (1/SM), W fp16 in SMEM.
// R7: 384 threads / 12 warps (3 per SMSP) with warp tile 48x64 (M_TILE=144):
// near-R5 crossbar traffic per row (4.8KB vs 4.0KB) but 50% more warps to
// overlap LDSM latency with HMMA. acc=96 regs -> no spills (R5 hit 255 cap).
// B fragments loaded just-in-time with 1-deep ping-pong prefetch.
// Single X buffer split by K-half (sin/cos) pipelined as in R5.
// ---------------------------------------------------------------------------

#define NT        384
#define MT        144
// SMEM layout (bytes):
//   W : 256 rows(c) x 256 k fp16, 512 B/row, XOR-swizzled -> 131072
//   X : 144 rows(m) x 256 k fp16, 512 B/row               ->  73728
//   F : 128 floats (freqs)                                ->    512
#define SW_OFF     0
#define SX_OFF     131072
#define SF_OFF     204800
#define SMEM_TOTAL 205312

static __device__ __forceinline__ uint32_t smem_u32(const void* p) {
    uint32_t a;
    asm("{ .reg .u64 t; cvta.to.shared.u64 t, %1; cvt.u32.u64 %0, t; }"
        : "=r"(a) : "l"(p));
    return a;
}

// byte offset of (row, 16B-chunk) in a 512 B/row tile with XOR swizzle:
// chunk' = chunk ^ (row & 7). Conflict-free for ldmatrix and the fills.
static __device__ __forceinline__ uint32_t swz(uint32_t row, uint32_t chunk) {
    return row * 512u + ((chunk ^ (row & 7u)) << 4);
}

#define LDSM_X4(r, addr) \
    asm volatile("ldmatrix.sync.aligned.m8n8.x4.shared.b16 {%0,%1,%2,%3}, [%4];" \
        : "=r"((r)[0]), "=r"((r)[1]), "=r"((r)[2]), "=r"((r)[3]) : "r"(addr))

#define MMA_16816(d, a, b0, b1) \
    asm volatile("mma.sync.aligned.m16n8k16.row.col.f32.f16.f16.f32 " \
        "{%0,%1,%2,%3}, {%4,%5,%6,%7}, {%8,%9}, {%0,%1,%2,%3};" \
        : "+f"((d)[0]), "+f"((d)[1]), "+f"((d)[2]), "+f"((d)[3]) \
        : "r"((a)[0]), "r"((a)[1]), "r"((a)[2]), "r"((a)[3]), \
          "r"(b0), "r"(b1))

// fill 4 freqs of sin (k=f) or cos (k=f+128) for one X row
template <bool USE_COS>
static __device__ __forceinline__ void fill_chunk4(char* xb, const float* sF,
                                                   float tv, int xrow, int f)
{
    const float4 fr = *reinterpret_cast<const float4*>(sF + f);
    float v0, v1, v2, v3, h, r, th;
    h = tv * fr.x; r = (h + 12582912.0f) - 12582912.0f;
    th = (h - r) * 6.283185307179586f; v0 = USE_COS ? __cosf(th) : __sinf(th);
    h = tv * fr.y; r = (h + 12582912.0f) - 12582912.0f;
    th = (h - r) * 6.283185307179586f; v1 = USE_COS ? __cosf(th) : __sinf(th);
    h = tv * fr.z; r = (h + 12582912.0f) - 12582912.0f;
    th = (h - r) * 6.283185307179586f; v2 = USE_COS ? __cosf(th) : __sinf(th);
    h = tv * fr.w; r = (h + 12582912.0f) - 12582912.0f;
    th = (h - r) * 6.283185307179586f; v3 = USE_COS ? __cosf(th) : __sinf(th);

    __half2 h0 = __floats2half2_rn(v0, v1);
    __half2 h1 = __floats2half2_rn(v2, v3);
    const uint32_t ch  = (uint32_t)(f >> 3) + (USE_COS ? 16u : 0u);
    const uint32_t off = ((uint32_t)(f >> 2) & 1u) << 3;   // 8B within chunk
    uint2 v;
    v.x = *reinterpret_cast<uint32_t*>(&h0);
    v.y = *reinterpret_cast<uint32_t*>(&h1);
    *reinterpret_cast<uint2*>(xb + swz((uint32_t)xrow, ch) + off) = v;
}

__global__ void __launch_bounds__(NT, 1)
fourier_mma_kernel(const float* __restrict__ t,
                   const float* __restrict__ freqs,
                   const float* __restrict__ As,
                   const float* __restrict__ Ac,
                   float* __restrict__ out,
                   int rows)
{
    extern __shared__ char smem[];
    char* sW  = smem + SW_OFF;
    char* sX  = smem + SX_OFF;
    float* sF = (float*)(smem + SF_OFF);
    const uint32_t uW = smem_u32(sW);
    const uint32_t uX = smem_u32(sX);

    const int tid  = threadIdx.x;
    const int lane = tid & 31;
    const int wid  = tid >> 5;

    // ---- one-time: freqs + W fp32->fp16 into swizzled SMEM ----------------
    if (tid < 128) sF[tid] = freqs[tid];
    for (int i = tid; i < 256 * 64; i += NT) {
        const int n  = i >> 6;
        const int j4 = i & 63;
        const int k0 = j4 << 2;
        const float* src = (k0 < 128) ? (As + n * 128 + k0)
                                      : (Ac + n * 128 + (k0 - 128));
        const float4 w = *reinterpret_cast<const float4*>(src);
        __half2 h0 = __floats2half2_rn(w.x, w.y);
        __half2 h1 = __floats2half2_rn(w.z, w.w);
        uint32_t byte = swz((uint32_t)n, (uint32_t)(j4 >> 1)) + ((uint32_t)(j4 & 1) << 3);
        uint2 v;
        v.x = *reinterpret_cast<uint32_t*>(&h0);
        v.y = *reinterpret_cast<uint32_t*>(&h1);
        *reinterpret_cast<uint2*>(sW + byte) = v;
    }

    // ---- per-thread constants ---------------------------------------------
    // X fill: threads 0..287 = 2 per row (144 rows), each covers 64 freqs.
    const bool filler = (tid < 288);
    const int  xrow   = tid >> 1;
    const int  f0     = (tid & 1) << 6;

    const int wm = wid >> 2;                   // warp grid: 3 (M) x 4 (N)
    const int wn = wid & 3;
    const int gid = lane >> 2, tig = lane & 3;

    const int aRow0   = wm * 48 + (lane & 15);
    const int aHi     = lane >> 4;
    const int bRowOff = (lane & 7) + ((lane >> 4) << 3);
    const int bHi     = (lane >> 3) & 1;

    const int numTiles = (rows + MT - 1) / MT;     // 1821 (last tile partial)
    const int stride   = gridDim.x;
    int tile = blockIdx.x;
    if (tile >= numTiles) return;

    __syncthreads();                           // W + freqs visible

    // ---- prologue: sin half of first tile ---------------------------------
    if (filler) {
        const int ri = tile * MT + xrow;
        const float tv = t[ri < rows ? ri : (rows - 1)];
        #pragma unroll
        for (int j = 0; j < 16; j++)
            fill_chunk4<false>(sX, sF, tv, xrow, f0 + j * 4);
    }
    __syncthreads();

    for (; tile < numTiles; tile += stride) {
        const int  nextTile = tile + stride;
        const bool hasNext  = nextTile < numTiles;
        const int m0 = tile * MT;
        float tvc = 0.0f, tvn = 0.0f;
        if (filler) {
            const int ri = m0 + xrow;
            tvc = t[ri < rows ? ri : (rows - 1)];                  // cos fill
            if (hasNext) {
                const int rj = nextTile * MT + xrow;
                tvn = t[rj < rows ? rj : (rows - 1)];              // sin fill
            }
        }

        float acc[3][8][4];
        #pragma unroll
        for (int mi = 0; mi < 3; mi++)
            #pragma unroll
            for (int ni = 0; ni < 8; ni++)
                #pragma unroll
                for (int q = 0; q < 4; q++) acc[mi][ni][q] = 0.0f;

        // ==== phase A: MMA ks 0..7 (sin half) + fill cos half of this tile ==
        #pragma unroll
        for (int ks = 0; ks < 8; ks++) {
            uint32_t a[3][4];
            #pragma unroll
            for (int mi = 0; mi < 3; mi++) {
                const uint32_t row = (uint32_t)(aRow0 + mi * 16);
                LDSM_X4(a[mi], uX + swz(row, (uint32_t)(ks * 2 + aHi)));
            }
            uint32_t bq[2][4];
            {
                const uint32_t n = (uint32_t)(wn * 64 + bRowOff);
                LDSM_X4(bq[0], uW + swz(n, (uint32_t)(ks * 2 + bHi)));
            }
            #pragma unroll
            for (int nt = 0; nt < 4; nt++) {
                if (nt < 3) {
                    const uint32_t n = (uint32_t)(wn * 64 + (nt + 1) * 16 + bRowOff);
                    LDSM_X4(bq[(nt + 1) & 1], uW + swz(n, (uint32_t)(ks * 2 + bHi)));
                }
                const uint32_t* bb = bq[nt & 1];
                #pragma unroll
                for (int mi = 0; mi < 3; mi++) {
                    MMA_16816(acc[mi][nt * 2],     a[mi], bb[0], bb[1]);
                    MMA_16816(acc[mi][nt * 2 + 1], a[mi], bb[2], bb[3]);
                }
            }
            if (filler) {
                fill_chunk4<true>(sX, sF, tvc, xrow, f0 + ks * 8);
                fill_chunk4<true>(sX, sF, tvc, xrow, f0 + ks * 8 + 4);
            }
        }
        __syncthreads();   // cos half ready; sin half free

        // ==== phase B: MMA ks 8..15 (cos half) + fill sin half of next tile =
        #pragma unroll
        for (int ks = 8; ks < 16; ks++) {
            uint32_t a[3][4];
            #pragma unroll
            for (int mi = 0; mi < 3; mi++) {
                const uint32_t row = (uint32_t)(aRow0 + mi * 16);
                LDSM_X4(a[mi], uX + swz(row, (uint32_t)(ks * 2 + aHi)));
            }
            uint32_t bq[2][4];
            {
                const uint32_t n = (uint32_t)(wn * 64 + bRowOff);
                LDSM_X4(bq[0], uW + swz(n, (uint32_t)(ks * 2 + bHi)));
            }
            #pragma unroll
            for (int nt = 0; nt < 4; nt++) {
                if (nt < 3) {
                    const uint32_t n = (uint32_t)(wn * 64 + (nt + 1) * 16 + bRowOff);
                    LDSM_X4(bq[(nt + 1) & 1], uW + swz(n, (uint32_t)(ks * 2 + bHi)));
                }
                const uint32_t* bb = bq[nt & 1];
                #pragma unroll
                for (int mi = 0; mi < 3; mi++) {
                    MMA_16816(acc[mi][nt * 2],     a[mi], bb[0], bb[1]);
                    MMA_16816(acc[mi][nt * 2 + 1], a[mi], bb[2], bb[3]);
                }
            }
            if (filler && hasNext) {
                const int j = (ks - 8) * 8;
                fill_chunk4<false>(sX, sF, tvn, xrow, f0 + j);
                fill_chunk4<false>(sX, sF, tvn, xrow, f0 + j + 4);
            }
        }
        __syncthreads();   // sin half of next tile ready; cos half free

        // ==== epilogue: regs -> gmem (STG.64), guarded for the tail tile ====
        #pragma unroll
        for (int mi = 0; mi < 3; mi++) {
            const int mrow = m0 + wm * 48 + mi * 16 + gid;
            if (mrow + 8 < rows) {
                float* o0 = out + (size_t)mrow * 256 + wn * 64 + tig * 2;
                #pragma unroll
                for (int ni = 0; ni < 8; ni++) {
                    float2 v0, v1;
                    v0.x = acc[mi][ni][0]; v0.y = acc[mi][ni][1];
                    v1.x = acc[mi][ni][2]; v1.y = acc[mi][ni][3];
                    *reinterpret_cast<float2*>(o0 + ni * 8)        = v0;  // row m
                    *reinterpret_cast<float2*>(o0 + ni * 8 + 2048) = v1;  // row m+8
                }
            } else {
                float* o0 = out + (size_t)mrow * 256 + wn * 64 + tig * 2;
                #pragma unroll
                for (int ni = 0; ni < 8; ni++) {
                    if (mrow < rows) {
                        float2 v0;
                        v0.x = acc[mi][ni][0]; v0.y = acc[mi][ni][1];
                        *reinterpret_cast<float2*>(o0 + ni * 8) = v0;
                    }
                    if (mrow + 8 < rows) {
                        float2 v1;
                        v1.x = acc[mi][ni][2]; v1.y = acc[mi][ni][3];
                        *reinterpret_cast<float2*>(o0 + ni * 8 + 2048) = v1;
                    }
                }
            }
        }
    }
}

extern "C" void kernel_launch(void* const* d_in, const int* in_sizes, int n_in,
                              void* d_out, int out_size)
{
    const float* t     = (const float*)d_in[0];
    const float* freqs = (const float*)d_in[1];
    const float* As    = (const float*)d_in[2];
    const float* Ac    = (const float*)d_in[3];
    float* out         = (float*)d_out;

    int sm_count = 148;
    cudaDeviceGetAttribute(&sm_count, cudaDevAttrMultiProcessorCount, 0);
    cudaFuncSetAttribute(fourier_mma_kernel,
                         cudaFuncAttributeMaxDynamicSharedMemorySize, SMEM_TOTAL);

    const int rows = in_sizes[0];          // B*L = 262144
    fourier_mma_kernel<<<sm_count, NT, SMEM_TOTAL>>>(t, freqs, As, Ac, out, rows);
}